// round 12
// baseline (speedup 1.0000x reference)
#include <cuda_runtime.h>
#include <cuda_bf16.h>

// ---------------------------------------------------------------------------
// MATLABStyleEnhancement: dehaze + guided filter + percentile stretch
// B=8, C=3, H=W=512
// ---------------------------------------------------------------------------

#define Bn 8
#define Hh 512
#define Ww 512
#define NP (Hh * Ww)            // 262144 = 2^18
#define NBC (Bn * 3)            // 24
#define YSEG 16
#define H1BINS 16384
#define H2BINS 65536
// skew for 8-outputs-per-thread stride: conflict-free for float4 (36t words ->
// 4t mod 32 distinct in 8-lane phase) and float2 (18t mod 32 distinct in 16 lanes)
#define SK8(i) ((i) + ((i) >> 3))

// ------------------------- device scratch ----------------------------------
__device__ float4 g_hA[Bn * NP];         // stage-1 box sums (g, tg, g*tg, g*g)
__device__ float2 g_ab[Bn * NP];         // (a, b)
__device__ float2 g_hB[Bn * NP];         // stage-2 box sums (a, b)
__device__ float  g_J[NBC * NP];
__device__ __align__(16) unsigned g_hist1[NBC * H1BINS];
__device__ __align__(16) unsigned g_hist2[NBC * 2 * H2BINS];
__device__ int g_selPrefix[NBC * 2];
__device__ unsigned g_selRank[NBC * 2];
__device__ float g_plow[NBC];
__device__ float g_phigh[NBC];

#define H1_BLOCKS (Bn * Hh / 2)                       // 2048
#define ZERO_ELTS ((NBC * H1BINS + NBC * 2 * H2BINS) / 4)   // 884736 uint4
#define ZERO_BLOCKS (ZERO_ELTS / 128)                 // 6912

__device__ __forceinline__ int reflect(int i, int n) {
    if (i < 0) i = -i;
    if (i >= n) i = 2 * n - 2 - i;
    return i;
}

__device__ __forceinline__ int get_r(const int* rp) {
    int r = rp ? *rp : 15;
    return max(1, min(r, 50));
}

// warp-aggregated histogram add; key must be < 0x10000; all 32 lanes execute.
__device__ __forceinline__ void whist_add(unsigned* bucket_base, int key, bool participate) {
    int lane = threadIdx.x & 31;
    int mk = participate ? key : (0x10000 + lane);   // unique sentinel for non-participants
    unsigned m = __match_any_sync(0xFFFFFFFFu, mk);
    if (participate && lane == (__ffs(m) - 1))
        atomicAdd(&bucket_base[key], (unsigned)__popc(m));
}

// ---- 1. fused: zero hists + t0/gray/tg + horizontal box sums (stage 1) -----
// blocks [0, H1_BLOCKS): h1 work, 2 rows per block, 8 outputs/thread
// blocks [H1_BLOCKS, H1_BLOCKS+ZERO_BLOCKS): zero the histograms
__global__ void __launch_bounds__(128)
h1z_kernel(const float* __restrict__ img,
           const float* __restrict__ omega,
           const float* __restrict__ atm,
           const int* rp) {
    if (blockIdx.x >= H1_BLOCKS) {
        int zi = (blockIdx.x - H1_BLOCKS) * 128 + threadIdx.x;
        const int n1 = NBC * H1BINS / 4;
        uint4 z = make_uint4(0u, 0u, 0u, 0u);
        if (zi < n1) ((uint4*)g_hist1)[zi] = z;
        else ((uint4*)g_hist2)[zi - n1] = z;
        return;
    }

    __shared__ float t0p[Ww], t00[Ww], t01[Ww];   // t0 rows: y0-1 (refl), y0, y0+1
    __shared__ float gs0[Ww], gs1[Ww], tg0[Ww], tg1[Ww];
    __shared__ float4 s4[2][704];                 // SK8(611)=687 max

    int r = get_r(rp);
    int k2r = 2 * r;
    int bi = blockIdx.x;
    int b = bi >> 8;                  // 256 row-pairs per batch
    int y0 = (bi & 255) * 2;
    int plen = Ww + k2r;
    int tid = threadIdx.x;

    float ra = 1.0f / (atm[b * 3 + 0] + 1e-8f);
    float rg = 1.0f / (atm[b * 3 + 1] + 1e-8f);
    float rb = 1.0f / (atm[b * 3 + 2] + 1e-8f);
    float om = omega[b];
    const float* ib = img + b * 3 * NP;
    int rowp = (y0 > 0 ? y0 - 1 : 0) * Ww;
    int row0 = y0 * Ww;
    int row1 = (y0 + 1) * Ww;

    // phase A: t0 for 3 rows + gray for 2 rows
    for (int x = tid; x < Ww; x += 128) {
        float p0 = ib[rowp + x], p1 = ib[NP + rowp + x], p2 = ib[2 * NP + rowp + x];
        float c0 = ib[row0 + x], c1 = ib[NP + row0 + x], c2 = ib[2 * NP + row0 + x];
        float d0 = ib[row1 + x], d1 = ib[NP + row1 + x], d2 = ib[2 * NP + row1 + x];
        t0p[x] = 1.0f - om * fminf(fminf(p0 * ra, p1 * rg), p2 * rb);
        t00[x] = 1.0f - om * fminf(fminf(c0 * ra, c1 * rg), c2 * rb);
        t01[x] = 1.0f - om * fminf(fminf(d0 * ra, d1 * rg), d2 * rb);
        gs0[x] = c0 * 0.299f + c1 * 0.587f + c2 * 0.114f;
        gs1[x] = d0 * 0.299f + d1 * 0.587f + d2 * 0.114f;
    }
    __syncthreads();

    // phase B: tg for both rows
    for (int x = tid; x < Ww; x += 128) {
        // row y0: tx from t0 row (y0-1 | y0 if y0==0); wy vs row y0 (skip if y0==0)
        float tu = t0p[x];
        float tx = (x == 0) ? tu : t0p[x - 1] * expf(-fabsf(tu - t0p[x - 1]));
        tg0[x] = (y0 > 0) ? tx * expf(-fabsf(t00[x] - tu)) : tx;
        // row y0+1: tx from row y0; wy vs row y0+1 (always, since y0+1 >= 1)
        float tu1 = t00[x];
        float tx1 = (x == 0) ? tu1 : t00[x - 1] * expf(-fabsf(tu1 - t00[x - 1]));
        tg1[x] = tx1 * expf(-fabsf(t01[x] - tu1));
    }
    __syncthreads();

    // phase C: padded float4 windows for both rows
    for (int ii = tid; ii < plen; ii += 128) {
        int x = reflect(ii - r, Ww);
        float g0 = gs0[x], t0v = tg0[x];
        float g1 = gs1[x], t1v = tg1[x];
        s4[0][SK8(ii)] = make_float4(g0, t0v, g0 * t0v, g0 * g0);
        s4[1][SK8(ii)] = make_float4(g1, t1v, g1 * t1v, g1 * g1);
    }
    __syncthreads();

    // phase D: sliding sums; 64-thread group per row, 8 outputs/thread
    int g = tid >> 6;
    int t64 = tid & 63;
    int x0 = t64 * 8;
    const float4* sp = s4[g];
    int base = (b * Hh + y0 + g) * Ww;

    float4 s = make_float4(0.f, 0.f, 0.f, 0.f);
    for (int j = 0; j <= k2r; j++) {
        float4 v = sp[SK8(x0 + j)];
        s.x += v.x; s.y += v.y; s.z += v.z; s.w += v.w;
    }
    #pragma unroll
    for (int u = 0; u < 8; u++) {
        int x = x0 + u;
        g_hA[base + x] = s;
        if (u < 7) {
            float4 a = sp[SK8(x + k2r + 1)];
            float4 d = sp[SK8(x)];
            s.x += a.x - d.x; s.y += a.y - d.y;
            s.z += a.z - d.z; s.w += a.w - d.w;
        }
    }
}

// ------------------- 2. vertical box sums (stage 1) -> a,b ------------------
__global__ void v1_kernel(const int* rp) {
    int r = get_r(rp);
    int b = blockIdx.z;
    int x = blockIdx.x * 256 + threadIdx.x;     // cols x and x+128
    int y0 = blockIdx.y * YSEG;
    int pb = b * NP;

    float4 s0 = make_float4(0.f, 0.f, 0.f, 0.f);
    float4 s1 = make_float4(0.f, 0.f, 0.f, 0.f);
    for (int j = -r; j <= r; j++) {
        int row = pb + reflect(y0 + j, Hh) * Ww;
        float4 h0 = g_hA[row + x];
        float4 h1 = g_hA[row + x + 128];
        s0.x += h0.x; s0.y += h0.y; s0.z += h0.z; s0.w += h0.w;
        s1.x += h1.x; s1.y += h1.y; s1.z += h1.z; s1.w += h1.w;
    }
    float k = (float)(2 * r + 1);
    float inv = 1.0f / (k * k);

    #pragma unroll 4
    for (int y = y0; y < y0 + YSEG; y++) {
        {
            float mI = s0.x * inv, mp = s0.y * inv, mIp = s0.z * inv, mGG = s0.w * inv;
            float a = (mIp - mI * mp) / ((mGG - mI * mI) + 0.5f);
            g_ab[pb + y * Ww + x] = make_float2(a, mp - a * mI);
        }
        {
            float mI = s1.x * inv, mp = s1.y * inv, mIp = s1.z * inv, mGG = s1.w * inv;
            float a = (mIp - mI * mp) / ((mGG - mI * mI) + 0.5f);
            g_ab[pb + y * Ww + x + 128] = make_float2(a, mp - a * mI);
        }
        int rowa = pb + reflect(y + r + 1, Hh) * Ww;
        int rowo = pb + reflect(y - r, Hh) * Ww;
        float4 a0 = g_hA[rowa + x],       o0 = g_hA[rowo + x];
        float4 a1 = g_hA[rowa + x + 128], o1 = g_hA[rowo + x + 128];
        s0.x += a0.x - o0.x; s0.y += a0.y - o0.y; s0.z += a0.z - o0.z; s0.w += a0.w - o0.w;
        s1.x += a1.x - o1.x; s1.y += a1.y - o1.y; s1.z += a1.z - o1.z; s1.w += a1.w - o1.w;
    }
}

// ------------------- 3. horizontal box sums (stage 2, float2) ---------------
// 2 rows per block, 8 outputs/thread
__global__ void __launch_bounds__(128) h2_kernel(const int* rp) {
    __shared__ float2 s2[2][704];
    int r = get_r(rp);
    int k2r = 2 * r;
    int base0 = blockIdx.x * 2 * Ww;            // first of two consecutive rows
    int plen = Ww + k2r;
    int tid = threadIdx.x;

    for (int ii = tid; ii < plen; ii += 128) {
        int x = reflect(ii - r, Ww);
        s2[0][SK8(ii)] = g_ab[base0 + x];
        s2[1][SK8(ii)] = g_ab[base0 + Ww + x];
    }
    __syncthreads();

    int g = tid >> 6;
    int t64 = tid & 63;
    int x0 = t64 * 8;
    const float2* sp = s2[g];
    int base = base0 + g * Ww;

    float2 s = make_float2(0.f, 0.f);
    for (int j = 0; j <= k2r; j++) {
        float2 v = sp[SK8(x0 + j)];
        s.x += v.x; s.y += v.y;
    }
    #pragma unroll
    for (int u = 0; u < 8; u++) {
        int x = x0 + u;
        g_hB[base + x] = s;
        if (u < 7) {
            float2 a = sp[SK8(x + k2r + 1)];
            float2 d = sp[SK8(x)];
            s.x += a.x - d.x; s.y += a.y - d.y;
        }
    }
}

// --------- 4. vertical (stage 2) -> t_final -> J + pass-1 histogram ---------
__global__ void v2_kernel(const float* __restrict__ img,
                          const float* __restrict__ atm,
                          const int* rp) {
    int r = get_r(rp);
    int b = blockIdx.z;
    int x = blockIdx.x * 256 + threadIdx.x;     // cols x and x+128
    int y0 = blockIdx.y * YSEG;
    int pb = b * NP;
    float A0 = atm[b * 3 + 0], A1 = atm[b * 3 + 1], A2 = atm[b * 3 + 2];

    float2 s0 = make_float2(0.f, 0.f), s1 = make_float2(0.f, 0.f);
    for (int j = -r; j <= r; j++) {
        int row = pb + reflect(y0 + j, Hh) * Ww;
        float2 h0 = g_hB[row + x];
        float2 h1 = g_hB[row + x + 128];
        s0.x += h0.x; s0.y += h0.y;
        s1.x += h1.x; s1.y += h1.y;
    }
    float k = (float)(2 * r + 1);
    float inv = 1.0f / (k * k);
    const float* ib = img + b * 3 * NP;
    unsigned* h1c0 = &g_hist1[(b * 3 + 0) * H1BINS];
    unsigned* h1c1 = &g_hist1[(b * 3 + 1) * H1BINS];
    unsigned* h1c2 = &g_hist1[(b * 3 + 2) * H1BINS];

    for (int y = y0; y < y0 + YSEG; y++) {
        #pragma unroll
        for (int cc = 0; cc < 2; cc++) {
            int xx = x + cc * 128;
            float2 sv = cc ? s1 : s0;
            int po = y * Ww + xx;
            float c0 = ib[po], c1 = ib[NP + po], c2 = ib[2 * NP + po];
            float gray = c0 * 0.299f + c1 * 0.587f + c2 * 0.114f;
            float t = fminf(fmaxf(sv.x * inv * gray + sv.y * inv, 0.1f), 1.0f);
            float it = 1.0f / (t + 1e-8f);
            float J0 = fminf(fmaxf((c0 - A0) * it + A0, 0.f), 1.f);
            float J1 = fminf(fmaxf((c1 - A1) * it + A1, 0.f), 1.f);
            float J2 = fminf(fmaxf((c2 - A2) * it + A2, 0.f), 1.f);
            int jb = b * 3 * NP + po;
            g_J[jb] = J0; g_J[jb + NP] = J1; g_J[jb + 2 * NP] = J2;
            whist_add(h1c0, (int)(__float_as_uint(J0) >> 16), true);
            whist_add(h1c1, (int)(__float_as_uint(J1) >> 16), true);
            whist_add(h1c2, (int)(__float_as_uint(J2) >> 16), true);
        }
        int rowa = pb + reflect(y + r + 1, Hh) * Ww;
        int rowo = pb + reflect(y - r, Hh) * Ww;
        float2 a0 = g_hB[rowa + x],       o0 = g_hB[rowo + x];
        float2 a1 = g_hB[rowa + x + 128], o1 = g_hB[rowo + x + 128];
        s0.x += a0.x - o0.x; s0.y += a0.y - o0.y;
        s1.x += a1.x - o1.x; s1.y += a1.y - o1.y;
    }
}

// ------------------- 5. select bucket from pass-1 histogram ------------------
__global__ void scan1_kernel(const float* __restrict__ Llow,
                             const float* __restrict__ Lhigh) {
    int bc = blockIdx.x >> 1;
    int sel = blockIdx.x & 1;
    int b = bc / 3;
    float L = sel ? Lhigh[b] : Llow[b];
    int kk = (int)((L / 100.0f) * (float)NP);   // matches (L/100*n).astype(int32)
    kk = max(0, min(kk, NP - 1));
    unsigned ks = (unsigned)kk;
    const unsigned* h = g_hist1 + bc * H1BINS;

    __shared__ unsigned part[256];
    int t = threadIdx.x;                        // 256 threads
    const int CH = H1BINS / 256;                // 64
    unsigned s = 0;
    for (int i = 0; i < CH; i++) s += h[t * CH + i];
    part[t] = s;
    __syncthreads();
    // inclusive Hillis-Steele scan
    for (int off = 1; off < 256; off <<= 1) {
        unsigned v = (t >= off) ? part[t - off] : 0u;
        __syncthreads();
        part[t] += v;
        __syncthreads();
    }
    unsigned excl = part[t] - s;
    if (ks >= excl && ks < excl + s) {
        unsigned cum = excl;
        for (int i = 0; i < CH; i++) {
            unsigned c = h[t * CH + i];
            if (ks < cum + c) {
                g_selPrefix[blockIdx.x] = t * CH + i;
                g_selRank[blockIdx.x] = ks - cum;
                break;
            }
            cum += c;
        }
    }
}

// ------------------- 6. pass-2 histogram (low 16 bits in bucket) ------------
__global__ void pass2_kernel() {
    __shared__ int sp0[NBC], sp1[NBC];
    if (threadIdx.x < NBC) {
        sp0[threadIdx.x] = g_selPrefix[2 * threadIdx.x];
        sp1[threadIdx.x] = g_selPrefix[2 * threadIdx.x + 1];
    }
    __syncthreads();
    int i4 = blockIdx.x * 256 + threadIdx.x;
    int bc = (i4 * 4) >> 18;                    // uniform per warp (NP/4 per bc)
    uint4 kv = ((const uint4*)g_J)[i4];
    unsigned* hl = &g_hist2[(bc * 2) * H2BINS];
    unsigned* hh = &g_hist2[(bc * 2 + 1) * H2BINS];
    int p0 = sp0[bc], p1 = sp1[bc];
    unsigned keys[4] = {kv.x, kv.y, kv.z, kv.w};
    #pragma unroll
    for (int u = 0; u < 4; u++) {
        int pre = (int)(keys[u] >> 16);
        int low = (int)(keys[u] & 0xFFFFu);
        whist_add(hl, low, pre == p0);
        whist_add(hh, low, pre == p1);
    }
}

// ------------------- 7. exact k-th value from pass-2 histogram ---------------
__global__ void scan2_kernel() {
    int idx = blockIdx.x;                       // bc*2 + sel
    const unsigned* h = g_hist2 + idx * H2BINS;
    unsigned ks = g_selRank[idx];

    __shared__ unsigned part[256];
    int t = threadIdx.x;
    const int CH = H2BINS / 256;                // 256
    unsigned s = 0;
    for (int i = 0; i < CH; i++) s += h[t * CH + i];
    part[t] = s;
    __syncthreads();
    for (int off = 1; off < 256; off <<= 1) {
        unsigned v = (t >= off) ? part[t - off] : 0u;
        __syncthreads();
        part[t] += v;
        __syncthreads();
    }
    unsigned excl = part[t] - s;
    if (ks >= excl && ks < excl + s) {
        unsigned cum = excl;
        for (int i = 0; i < CH; i++) {
            unsigned c = h[t * CH + i];
            if (ks < cum + c) {
                unsigned bits = ((unsigned)g_selPrefix[idx] << 16) | (unsigned)(t * CH + i);
                float v = __uint_as_float(bits);
                int bc = idx >> 1;
                if (idx & 1) g_phigh[bc] = v; else g_plow[bc] = v;
                break;
            }
            cum += c;
        }
    }
}

// ------------------- 8. final normalize (float4) ----------------------------
__global__ void final_kernel(float* __restrict__ out) {
    int i4 = blockIdx.x * 256 + threadIdx.x;
    int bc = (i4 * 4) >> 18;
    float pl = g_plow[bc], ph = g_phigh[bc];
    float sc = 1.0f / (ph - pl + 1e-8f);
    float4 v = ((const float4*)g_J)[i4];
    float4 o;
    o.x = fminf(fmaxf((fminf(fmaxf(v.x, pl), ph) - pl) * sc, 0.f), 1.f);
    o.y = fminf(fmaxf((fminf(fmaxf(v.y, pl), ph) - pl) * sc, 0.f), 1.f);
    o.z = fminf(fmaxf((fminf(fmaxf(v.z, pl), ph) - pl) * sc, 0.f), 1.f);
    o.w = fminf(fmaxf((fminf(fmaxf(v.w, pl), ph) - pl) * sc, 0.f), 1.f);
    ((float4*)out)[i4] = o;
}

// ---------------------------------------------------------------------------
extern "C" void kernel_launch(void* const* d_in, const int* in_sizes, int n_in,
                              void* d_out, int out_size) {
    const float* img   = (const float*)d_in[0];
    const float* omega = (const float*)d_in[1];
    const float* atm   = (const float*)d_in[2];
    const float* Llow  = (const float*)d_in[3];
    const float* Lhigh = (const float*)d_in[4];
    const int*   rp    = (n_in > 5) ? (const int*)d_in[5] : nullptr;
    float* out = (float*)d_out;

    h1z_kernel<<<H1_BLOCKS + ZERO_BLOCKS, 128>>>(img, omega, atm, rp);
    v1_kernel<<<dim3(Ww / 256, Hh / YSEG, Bn), 128>>>(rp);
    h2_kernel<<<Bn * Hh / 2, 128>>>(rp);
    v2_kernel<<<dim3(Ww / 256, Hh / YSEG, Bn), 128>>>(img, atm, rp);
    scan1_kernel<<<NBC * 2, 256>>>(Llow, Lhigh);
    pass2_kernel<<<NBC * NP / 1024, 256>>>();
    scan2_kernel<<<NBC * 2, 256>>>();
    final_kernel<<<NBC * NP / 1024, 256>>>(out);
}

// round 14
// speedup vs baseline: 1.5778x; 1.5778x over previous
#include <cuda_runtime.h>
#include <cuda_bf16.h>

// ---------------------------------------------------------------------------
// MATLABStyleEnhancement: dehaze + guided filter + percentile stretch
// B=8, C=3, H=W=512
// ---------------------------------------------------------------------------

#define Bn 8
#define Hh 512
#define Ww 512
#define NP (Hh * Ww)            // 262144 = 2^18
#define NBC (Bn * 3)            // 24
#define YSEG 8
#define H1BINS 16384
#define H2BINS 65536
// skew matched to 4-outputs-per-thread stride: lane word strides 20 (f4) / 10 (f2)
// are conflict-free within LDS.128 / LDS.64 phases (distinct mod-32 banks).
#define SK(i) ((i) + ((i) >> 2))

// ------------------------- device scratch ----------------------------------
__device__ float4 g_hA[Bn * NP];         // stage-1 box sums (g, tg, g*tg, g*g)
__device__ float2 g_ab[Bn * NP];         // (a, b)
__device__ float2 g_hB[Bn * NP];         // stage-2 box sums (a, b)
__device__ float  g_J[NBC * NP];
__device__ __align__(16) unsigned g_hist1[NBC * H1BINS];
__device__ __align__(16) unsigned g_hist2[NBC * 2 * H2BINS];
__device__ int g_selPrefix[NBC * 2];
__device__ unsigned g_selRank[NBC * 2];
__device__ float g_plow[NBC];
__device__ float g_phigh[NBC];

__device__ __forceinline__ int reflect(int i, int n) {
    if (i < 0) i = -i;
    if (i >= n) i = 2 * n - 2 - i;
    return i;
}

__device__ __forceinline__ int get_r(const int* rp) {
    int r = rp ? *rp : 15;
    return max(1, min(r, 50));
}

// warp-aggregated histogram add; key must be < 0x10000; all 32 lanes execute.
__device__ __forceinline__ void whist_add(unsigned* bucket_base, int key, bool participate) {
    int lane = threadIdx.x & 31;
    int mk = participate ? key : (0x10000 + lane);   // unique sentinel for non-participants
    unsigned m = __match_any_sync(0xFFFFFFFFu, mk);
    if (participate && lane == (__ffs(m) - 1))
        atomicAdd(&bucket_base[key], (unsigned)__popc(m));
}

// ------------------- 0. zero histograms ------------------------------------
__global__ void zero_kernel() {
    const int n1 = NBC * H1BINS / 4;           // 98304 uint4
    int i = blockIdx.x * blockDim.x + threadIdx.x;
    uint4 z = make_uint4(0u, 0u, 0u, 0u);
    if (i < n1) ((uint4*)g_hist1)[i] = z;
    else ((uint4*)g_hist2)[i - n1] = z;
}

// ---- 1. fused: t0/gray/tg from img + horizontal box sums (stage 1) ---------
__global__ void h1_kernel(const float* __restrict__ img,
                          const float* __restrict__ omega,
                          const float* __restrict__ atm,
                          const int* rp) {
    __shared__ float t0c[Ww], t0u[Ww], grow[Ww], tgrow[Ww];
    __shared__ float4 s4[768];                  // SK(611)=763 max
    int r = get_r(rp);
    int k2r = 2 * r;
    int b = blockIdx.x >> 9;
    int y = blockIdx.x & 511;
    int base = blockIdx.x * Ww;                 // (b*512+y)*512
    int plen = Ww + k2r;
    int tid = threadIdx.x;

    float ra = 1.0f / (atm[b * 3 + 0] + 1e-8f);
    float rg = 1.0f / (atm[b * 3 + 1] + 1e-8f);
    float rb = 1.0f / (atm[b * 3 + 2] + 1e-8f);
    float om = omega[b];
    const float* ib = img + b * 3 * NP;
    int rowc = y * Ww;
    int rowu = (y > 0 ? y - 1 : 0) * Ww;

    // phase A: t0 rows + gray row
    for (int x = tid; x < Ww; x += 128) {
        float c0 = ib[rowc + x], c1 = ib[NP + rowc + x], c2 = ib[2 * NP + rowc + x];
        float u0 = ib[rowu + x], u1 = ib[NP + rowu + x], u2 = ib[2 * NP + rowu + x];
        t0c[x] = 1.0f - om * fminf(fminf(c0 * ra, c1 * rg), c2 * rb);
        t0u[x] = 1.0f - om * fminf(fminf(u0 * ra, u1 * rg), u2 * rb);
        grow[x] = c0 * 0.299f + c1 * 0.587f + c2 * 0.114f;
    }
    __syncthreads();

    // phase B: tg row
    for (int x = tid; x < Ww; x += 128) {
        float tu = t0u[x];
        float tx = (x == 0) ? tu
                 : t0u[x - 1] * expf(-fabsf(tu - t0u[x - 1]));
        tgrow[x] = (y > 0) ? tx * expf(-fabsf(t0c[x] - tu)) : tx;
    }
    __syncthreads();

    // phase C: padded float4 window
    for (int ii = tid; ii < plen; ii += 128) {
        int x = reflect(ii - r, Ww);
        float g = grow[x], t = tgrow[x];
        s4[SK(ii)] = make_float4(g, t, g * t, g * g);
    }
    __syncthreads();

    // phase D: sliding sums, 4 outputs per thread
    int x0 = tid * 4;
    float4 s = make_float4(0.f, 0.f, 0.f, 0.f);
    for (int j = 0; j <= k2r; j++) {
        float4 v = s4[SK(x0 + j)];
        s.x += v.x; s.y += v.y; s.z += v.z; s.w += v.w;
    }
    #pragma unroll
    for (int u = 0; u < 4; u++) {
        int x = x0 + u;
        g_hA[base + x] = s;
        if (u < 3) {
            float4 a = s4[SK(x + k2r + 1)];
            float4 d = s4[SK(x)];
            s.x += a.x - d.x; s.y += a.y - d.y;
            s.z += a.z - d.z; s.w += a.w - d.w;
        }
    }
}

// ------------------- 2. vertical box sums (stage 1) -> a,b ------------------
__global__ void v1_kernel(const int* rp) {
    int r = get_r(rp);
    int b = blockIdx.z;
    int x = blockIdx.x * 256 + threadIdx.x;     // cols x and x+128
    int y0 = blockIdx.y * YSEG;
    int pb = b * NP;

    float4 s0 = make_float4(0.f, 0.f, 0.f, 0.f);
    float4 s1 = make_float4(0.f, 0.f, 0.f, 0.f);
    for (int j = -r; j <= r; j++) {
        int row = pb + reflect(y0 + j, Hh) * Ww;
        float4 h0 = g_hA[row + x];
        float4 h1 = g_hA[row + x + 128];
        s0.x += h0.x; s0.y += h0.y; s0.z += h0.z; s0.w += h0.w;
        s1.x += h1.x; s1.y += h1.y; s1.z += h1.z; s1.w += h1.w;
    }
    float k = (float)(2 * r + 1);
    float inv = 1.0f / (k * k);

    #pragma unroll
    for (int y = y0; y < y0 + YSEG; y++) {
        {
            float mI = s0.x * inv, mp = s0.y * inv, mIp = s0.z * inv, mGG = s0.w * inv;
            float a = (mIp - mI * mp) / ((mGG - mI * mI) + 0.5f);
            g_ab[pb + y * Ww + x] = make_float2(a, mp - a * mI);
        }
        {
            float mI = s1.x * inv, mp = s1.y * inv, mIp = s1.z * inv, mGG = s1.w * inv;
            float a = (mIp - mI * mp) / ((mGG - mI * mI) + 0.5f);
            g_ab[pb + y * Ww + x + 128] = make_float2(a, mp - a * mI);
        }
        int rowa = pb + reflect(y + r + 1, Hh) * Ww;
        int rowo = pb + reflect(y - r, Hh) * Ww;
        float4 a0 = g_hA[rowa + x],       o0 = g_hA[rowo + x];
        float4 a1 = g_hA[rowa + x + 128], o1 = g_hA[rowo + x + 128];
        s0.x += a0.x - o0.x; s0.y += a0.y - o0.y; s0.z += a0.z - o0.z; s0.w += a0.w - o0.w;
        s1.x += a1.x - o1.x; s1.y += a1.y - o1.y; s1.z += a1.z - o1.z; s1.w += a1.w - o1.w;
    }
}

// ------------------- 3. horizontal box sums (stage 2, float2) ---------------
__global__ void h2_kernel(const int* rp) {
    __shared__ float2 s2[768];
    int r = get_r(rp);
    int k2r = 2 * r;
    int base = blockIdx.x * Ww;
    int plen = Ww + k2r;

    for (int ii = threadIdx.x; ii < plen; ii += 128) {
        int x = reflect(ii - r, Ww);
        s2[SK(ii)] = g_ab[base + x];
    }
    __syncthreads();

    int x0 = threadIdx.x * 4;
    float2 s = make_float2(0.f, 0.f);
    for (int j = 0; j <= k2r; j++) {
        float2 v = s2[SK(x0 + j)];
        s.x += v.x; s.y += v.y;
    }
    #pragma unroll
    for (int u = 0; u < 4; u++) {
        int x = x0 + u;
        g_hB[base + x] = s;
        if (u < 3) {
            float2 a = s2[SK(x + k2r + 1)];
            float2 d = s2[SK(x)];
            s.x += a.x - d.x; s.y += a.y - d.y;
        }
    }
}

// --------- 4. vertical (stage 2) -> t_final -> J + pass-1 histogram ---------
__global__ void v2_kernel(const float* __restrict__ img,
                          const float* __restrict__ atm,
                          const int* rp) {
    int r = get_r(rp);
    int b = blockIdx.z;
    int x = blockIdx.x * 256 + threadIdx.x;     // cols x and x+128
    int y0 = blockIdx.y * YSEG;
    int pb = b * NP;
    float A0 = atm[b * 3 + 0], A1 = atm[b * 3 + 1], A2 = atm[b * 3 + 2];

    float2 s0 = make_float2(0.f, 0.f), s1 = make_float2(0.f, 0.f);
    for (int j = -r; j <= r; j++) {
        int row = pb + reflect(y0 + j, Hh) * Ww;
        float2 h0 = g_hB[row + x];
        float2 h1 = g_hB[row + x + 128];
        s0.x += h0.x; s0.y += h0.y;
        s1.x += h1.x; s1.y += h1.y;
    }
    float k = (float)(2 * r + 1);
    float inv = 1.0f / (k * k);
    const float* ib = img + b * 3 * NP;
    unsigned* h1c0 = &g_hist1[(b * 3 + 0) * H1BINS];
    unsigned* h1c1 = &g_hist1[(b * 3 + 1) * H1BINS];
    unsigned* h1c2 = &g_hist1[(b * 3 + 2) * H1BINS];

    for (int y = y0; y < y0 + YSEG; y++) {
        #pragma unroll
        for (int cc = 0; cc < 2; cc++) {
            int xx = x + cc * 128;
            float2 sv = cc ? s1 : s0;
            int po = y * Ww + xx;
            float c0 = ib[po], c1 = ib[NP + po], c2 = ib[2 * NP + po];
            float gray = c0 * 0.299f + c1 * 0.587f + c2 * 0.114f;
            float t = fminf(fmaxf(sv.x * inv * gray + sv.y * inv, 0.1f), 1.0f);
            float it = 1.0f / (t + 1e-8f);
            float J0 = fminf(fmaxf((c0 - A0) * it + A0, 0.f), 1.f);
            float J1 = fminf(fmaxf((c1 - A1) * it + A1, 0.f), 1.f);
            float J2 = fminf(fmaxf((c2 - A2) * it + A2, 0.f), 1.f);
            int jb = b * 3 * NP + po;
            g_J[jb] = J0; g_J[jb + NP] = J1; g_J[jb + 2 * NP] = J2;
            whist_add(h1c0, (int)(__float_as_uint(J0) >> 16), true);
            whist_add(h1c1, (int)(__float_as_uint(J1) >> 16), true);
            whist_add(h1c2, (int)(__float_as_uint(J2) >> 16), true);
        }
        int rowa = pb + reflect(y + r + 1, Hh) * Ww;
        int rowo = pb + reflect(y - r, Hh) * Ww;
        float2 a0 = g_hB[rowa + x],       o0 = g_hB[rowo + x];
        float2 a1 = g_hB[rowa + x + 128], o1 = g_hB[rowo + x + 128];
        s0.x += a0.x - o0.x; s0.y += a0.y - o0.y;
        s1.x += a1.x - o1.x; s1.y += a1.y - o1.y;
    }
}

// ------------------- 5. select bucket from pass-1 histogram ------------------
__global__ void scan1_kernel(const float* __restrict__ Llow,
                             const float* __restrict__ Lhigh) {
    int bc = blockIdx.x >> 1;
    int sel = blockIdx.x & 1;
    int b = bc / 3;
    float L = sel ? Lhigh[b] : Llow[b];
    int kk = (int)((L / 100.0f) * (float)NP);   // matches (L/100*n).astype(int32)
    kk = max(0, min(kk, NP - 1));
    unsigned ks = (unsigned)kk;
    const unsigned* h = g_hist1 + bc * H1BINS;

    __shared__ unsigned part[257];
    int t = threadIdx.x;                        // 256 threads
    const int CH = H1BINS / 256;                // 64
    unsigned s = 0;
    for (int i = 0; i < CH; i++) s += h[t * CH + i];
    part[t] = s;
    __syncthreads();
    if (t == 0) {
        unsigned run = 0;
        for (int i = 0; i < 256; i++) { unsigned v = part[i]; part[i] = run; run += v; }
        part[256] = run;
    }
    __syncthreads();
    if (ks >= part[t] && ks < part[t + 1]) {
        unsigned cum = part[t];
        for (int i = 0; i < CH; i++) {
            unsigned c = h[t * CH + i];
            if (ks < cum + c) {
                g_selPrefix[blockIdx.x] = t * CH + i;
                g_selRank[blockIdx.x] = ks - cum;
                break;
            }
            cum += c;
        }
    }
}

// ------------------- 6. pass-2 histogram (low 16 bits in bucket) ------------
__global__ void pass2_kernel() {
    __shared__ int sp0[NBC], sp1[NBC];
    if (threadIdx.x < NBC) {
        sp0[threadIdx.x] = g_selPrefix[2 * threadIdx.x];
        sp1[threadIdx.x] = g_selPrefix[2 * threadIdx.x + 1];
    }
    __syncthreads();
    int i4 = blockIdx.x * 256 + threadIdx.x;
    int bc = (i4 * 4) >> 18;                    // uniform per warp (NP/4 per bc)
    uint4 kv = ((const uint4*)g_J)[i4];
    unsigned* hl = &g_hist2[(bc * 2) * H2BINS];
    unsigned* hh = &g_hist2[(bc * 2 + 1) * H2BINS];
    int p0 = sp0[bc], p1 = sp1[bc];
    unsigned keys[4] = {kv.x, kv.y, kv.z, kv.w};
    #pragma unroll
    for (int u = 0; u < 4; u++) {
        int pre = (int)(keys[u] >> 16);
        int low = (int)(keys[u] & 0xFFFFu);
        whist_add(hl, low, pre == p0);
        whist_add(hh, low, pre == p1);
    }
}

// ------------------- 7. exact k-th value from pass-2 histogram ---------------
__global__ void scan2_kernel() {
    int idx = blockIdx.x;                       // bc*2 + sel
    const unsigned* h = g_hist2 + idx * H2BINS;
    unsigned ks = g_selRank[idx];

    __shared__ unsigned part[257];
    int t = threadIdx.x;
    const int CH = H2BINS / 256;                // 256
    unsigned s = 0;
    for (int i = 0; i < CH; i++) s += h[t * CH + i];
    part[t] = s;
    __syncthreads();
    if (t == 0) {
        unsigned run = 0;
        for (int i = 0; i < 256; i++) { unsigned v = part[i]; part[i] = run; run += v; }
        part[256] = run;
    }
    __syncthreads();
    if (ks >= part[t] && ks < part[t + 1]) {
        unsigned cum = part[t];
        for (int i = 0; i < CH; i++) {
            unsigned c = h[t * CH + i];
            if (ks < cum + c) {
                unsigned bits = ((unsigned)g_selPrefix[idx] << 16) | (unsigned)(t * CH + i);
                float v = __uint_as_float(bits);
                int bc = idx >> 1;
                if (idx & 1) g_phigh[bc] = v; else g_plow[bc] = v;
                break;
            }
            cum += c;
        }
    }
}

// ------------------- 8. final normalize (float4) ----------------------------
__global__ void final_kernel(float* __restrict__ out) {
    int i4 = blockIdx.x * 256 + threadIdx.x;
    int bc = (i4 * 4) >> 18;
    float pl = g_plow[bc], ph = g_phigh[bc];
    float sc = 1.0f / (ph - pl + 1e-8f);
    float4 v = ((const float4*)g_J)[i4];
    float4 o;
    o.x = fminf(fmaxf((fminf(fmaxf(v.x, pl), ph) - pl) * sc, 0.f), 1.f);
    o.y = fminf(fmaxf((fminf(fmaxf(v.y, pl), ph) - pl) * sc, 0.f), 1.f);
    o.z = fminf(fmaxf((fminf(fmaxf(v.z, pl), ph) - pl) * sc, 0.f), 1.f);
    o.w = fminf(fmaxf((fminf(fmaxf(v.w, pl), ph) - pl) * sc, 0.f), 1.f);
    ((float4*)out)[i4] = o;
}

// ---------------------------------------------------------------------------
extern "C" void kernel_launch(void* const* d_in, const int* in_sizes, int n_in,
                              void* d_out, int out_size) {
    const float* img   = (const float*)d_in[0];
    const float* omega = (const float*)d_in[1];
    const float* atm   = (const float*)d_in[2];
    const float* Llow  = (const float*)d_in[3];
    const float* Lhigh = (const float*)d_in[4];
    const int*   rp    = (n_in > 5) ? (const int*)d_in[5] : nullptr;
    float* out = (float*)d_out;

    zero_kernel<<<3456, 256>>>();
    h1_kernel<<<Bn * Hh, 128>>>(img, omega, atm, rp);
    v1_kernel<<<dim3(Ww / 256, Hh / YSEG, Bn), 128>>>(rp);
    h2_kernel<<<Bn * Hh, 128>>>(rp);
    v2_kernel<<<dim3(Ww / 256, Hh / YSEG, Bn), 128>>>(img, atm, rp);
    scan1_kernel<<<NBC * 2, 256>>>(Llow, Lhigh);
    pass2_kernel<<<NBC * NP / 1024, 256>>>();
    scan2_kernel<<<NBC * 2, 256>>>();
    final_kernel<<<NBC * NP / 1024, 256>>>(out);
}